// round 5
// baseline (speedup 1.0000x reference)
#include <cuda_runtime.h>
#include <cuda_fp16.h>
#include <cstdint>

#define N_ROWS 32768
#define D 64
#define K 1024
#define KPAD 88            // padded k-extent in halfs; row stride 176 B (conflict-free ldmatrix)
#define ROWB 176
#define TM 128             // rows per CTA
#define MARGIN_COARSE 4e-3f
#define MARGIN_TIE    3e-4f

__device__ float d_en[K];                        // fp32 ||e_k||^2 (ref-style mul-then-add)
__device__ float d_eT[K * D];                    // [k][d] fp32 (rescore / refine / gather)
__device__ __align__(16) __half d_Bh[K * KPAD];  // [k][KPAD] fp16 codebook (+aug en at col 64)
__device__ int   d_idx[N_ROWS];
__device__ float d_lossAcc;
__device__ int   d_flagCnt;
__device__ int   d_flagList[N_ROWS];
__device__ int   d_flag2Cnt;
__device__ int   d_flag2List[N_ROWS];

// ---------------- helpers ----------------
__device__ __forceinline__ uint32_t smem_u32(const void* p) {
    uint32_t a;
    asm("{ .reg .u64 t; cvta.to.shared.u64 t, %1; cvt.u32.u64 %0, t; }" : "=r"(a) : "l"(p));
    return a;
}
__device__ __forceinline__ void ldm_x4(uint32_t* r, uint32_t addr) {
    asm volatile("ldmatrix.sync.aligned.m8n8.x4.shared.b16 {%0,%1,%2,%3}, [%4];"
        : "=r"(r[0]), "=r"(r[1]), "=r"(r[2]), "=r"(r[3]) : "r"(addr));
}
__device__ __forceinline__ void mma_f16(float* d, const uint32_t* a, const uint32_t* b) {
    asm volatile("mma.sync.aligned.m16n8k16.row.col.f32.f16.f16.f32 "
        "{%0,%1,%2,%3}, {%4,%5,%6,%7}, {%8,%9}, {%0,%1,%2,%3};"
        : "+f"(d[0]), "+f"(d[1]), "+f"(d[2]), "+f"(d[3])
        : "r"(a[0]), "r"(a[1]), "r"(a[2]), "r"(a[3]), "r"(b[0]), "r"(b[1]));
}
__device__ __forceinline__ void cp_async16(uint32_t sdst, const void* gsrc) {
    asm volatile("cp.async.cg.shared.global [%0], [%1], 16;" :: "r"(sdst), "l"(gsrc) : "memory");
}
__device__ __forceinline__ void cp_commit() { asm volatile("cp.async.commit_group;" ::: "memory"); }
__device__ __forceinline__ void cp_wait0()  { asm volatile("cp.async.wait_group 0;" ::: "memory"); }

// ---------------- Kernel 0: prep ----------------
// Norms (mul-then-add sequential fp32), transpose to [k][d], fp16 codebook + aug col.
__global__ void prep_kernel(const float* __restrict__ emb) {
    int k = blockIdx.x * blockDim.x + threadIdx.x;
    if (k == 0) { d_lossAcc = 0.0f; d_flagCnt = 0; d_flag2Cnt = 0; }
    if (k < K) {
        float s = 0.0f;
        float fbuf[4];
        for (int dd = 0; dd < D; dd += 4) {
            #pragma unroll
            for (int u = 0; u < 4; u++) {
                float v = emb[(dd + u) * K + k];            // coalesced across lanes
                s = __fadd_rn(s, __fmul_rn(v, v));          // ref-style mul-then-add
                fbuf[u] = v;
            }
            *(float4*)(d_eT + k * D + dd) = make_float4(fbuf[0], fbuf[1], fbuf[2], fbuf[3]);
            __half h0 = __float2half(fbuf[0]), h1 = __float2half(fbuf[1]);
            __half h2 = __float2half(fbuf[2]), h3 = __float2half(fbuf[3]);
            *(uint2*)(d_Bh + k * KPAD + dd) = make_uint2(
                (uint32_t)__half_as_ushort(h0) | ((uint32_t)__half_as_ushort(h1) << 16),
                (uint32_t)__half_as_ushort(h2) | ((uint32_t)__half_as_ushort(h3) << 16));
        }
        d_en[k] = s;
        // aug col 64 = en (fp16); cols 65..87 = 0
        *(uint2*)(d_Bh + k * KPAD + 64) = make_uint2((uint32_t)__half_as_ushort(__float2half(s)), 0u);
        *(uint2*)(d_Bh + k * KPAD + 68) = make_uint2(0u, 0u);
        *(uint4*)(d_Bh + k * KPAD + 72) = make_uint4(0u, 0u, 0u, 0u);
        *(uint4*)(d_Bh + k * KPAD + 80) = make_uint4(0u, 0u, 0u, 0u);
    }
}

// ---------------- Kernel 1: fp16 HMMA coarse + fused argmin ----------------
// smem: A[128][88]h = 22528 B, B double buffer 2 x [64][88]h = 2 x 11264 B
#define S_A   0
#define S_B   22528
#define PLANE 11264
#define S_TOTAL 45056

__global__ __launch_bounds__(256, 2)
void gemm_argmin_kernel(const float* __restrict__ x) {
    extern __shared__ char smem[];
    uint32_t sb = smem_u32(smem);
    int tid = threadIdx.x;
    int lane = tid & 31, warp = tid >> 5;
    int m0 = warp * 16;
    int row0 = blockIdx.x * TM;

    // ---- A: x rows -> fp16 of (-2x), padded, aug col 64 = 1.0 ----
    #pragma unroll
    for (int i = 0; i < 8; i++) {
        int f = tid + i * 256;          // 2048 float4 = 128 rows x 16
        int row = f >> 4, j = f & 15;
        float4 v = *(const float4*)(x + (row0 + row) * D + 4 * j);
        __half h0 = __float2half(-2.0f * v.x), h1 = __float2half(-2.0f * v.y);
        __half h2 = __float2half(-2.0f * v.z), h3 = __float2half(-2.0f * v.w);
        *(uint2*)(smem + S_A + (uint32_t)row * ROWB + j * 8) = make_uint2(
            (uint32_t)__half_as_ushort(h0) | ((uint32_t)__half_as_ushort(h1) << 16),
            (uint32_t)__half_as_ushort(h2) | ((uint32_t)__half_as_ushort(h3) << 16));
    }
    if (tid < 128) {
        uint32_t base = S_A + (uint32_t)tid * ROWB + 128;   // byte offset of col 64
        *(uint4*)(smem + base)      = make_uint4(0x3C00u, 0u, 0u, 0u);   // 1.0h, zeros
        *(uint4*)(smem + base + 16) = make_uint4(0u, 0u, 0u, 0u);
        *(uint4*)(smem + base + 32) = make_uint4(0u, 0u, 0u, 0u);
    }

    // ---- B chunk loader via cp.async (flat copy, same [n][KPAD] layout) ----
    auto loadB = [&](int chunk) {
        uint32_t dst = sb + S_B + (uint32_t)(chunk & 1) * PLANE;
        const char* src = (const char*)(d_Bh + chunk * 64 * KPAD);
        #pragma unroll
        for (int i = 0; i < 3; i++) {
            int u = tid + i * 256;                 // 704 16B units
            if (u < 704) cp_async16(dst + 16 * u, src + 16 * u);
        }
        cp_commit();
    };

    loadB(0);
    cp_wait0();
    __syncthreads();

    // ---- per-lane ldmatrix addresses ----
    int r = lane & 7, q = lane >> 3;
    uint32_t aAddr = sb + S_A + (uint32_t)(m0 + r + ((q & 1) << 3)) * ROWB + ((q >> 1) << 4);
    uint32_t bOff = (uint32_t)(r + ((q >> 1) << 3)) * ROWB + ((q & 1) << 4);

    uint32_t ah[5][4];
    #pragma unroll
    for (int k = 0; k < 5; k++) ldm_x4(ah[k], aAddr + k * 32);

    float bA = 3.4e38f, b2A = 3.4e38f, bB = 3.4e38f, b2B = 3.4e38f;
    int iA = 0, iB = 0;

    #pragma unroll 1
    for (int c = 0; c < 16; c++) {
        if (c < 15) loadB(c + 1);     // async prefetch into other buffer

        uint32_t bbase = sb + S_B + (uint32_t)(c & 1) * PLANE + bOff;

        float acc[8][4];
        #pragma unroll
        for (int nb = 0; nb < 8; nb++)
            #pragma unroll
            for (int j = 0; j < 4; j++) acc[nb][j] = 0.0f;

        #pragma unroll
        for (int k = 0; k < 5; k++) {
            #pragma unroll
            for (int t = 0; t < 4; t++) {
                uint32_t bh[4];
                ldm_x4(bh, bbase + t * (16 * ROWB) + k * 32);
                mma_f16(acc[2*t],   ah[k], bh);
                mma_f16(acc[2*t+1], ah[k], bh + 2);
            }
        }

        // epilogue: acc == dist approx = en - 2 x.e
        int kbase = c * 64 + 2 * (lane & 3);
        #pragma unroll
        for (int nb = 0; nb < 8; nb++) {
            #pragma unroll
            for (int j = 0; j < 4; j++) {
                float v = acc[nb][j];
                int kidx = kbase + nb * 8 + (j & 1);
                if (j < 2) {
                    if (v < bA) { b2A = bA; bA = v; iA = kidx; } else b2A = fminf(b2A, v);
                } else {
                    if (v < bB) { b2B = bB; bB = v; iB = kidx; } else b2B = fminf(b2B, v);
                }
            }
        }
        cp_wait0();
        __syncthreads();
    }

    // ---- merge across the 4 lanes sharing each row ----
    #pragma unroll
    for (int off = 1; off <= 2; off <<= 1) {
        float ov = __shfl_xor_sync(0xffffffff, bA, off);
        float ov2 = __shfl_xor_sync(0xffffffff, b2A, off);
        int   oi = __shfl_xor_sync(0xffffffff, iA, off);
        if (ov < bA) { b2A = fminf(bA, ov2); bA = ov; iA = oi; } else b2A = fminf(b2A, ov);
        ov = __shfl_xor_sync(0xffffffff, bB, off);
        ov2 = __shfl_xor_sync(0xffffffff, b2B, off);
        oi = __shfl_xor_sync(0xffffffff, iB, off);
        if (ov < bB) { b2B = fminf(bB, ov2); bB = ov; iB = oi; } else b2B = fminf(b2B, ov);
    }
    if ((lane & 3) == 0) {
        int rowA = row0 + m0 + (lane >> 2);
        d_idx[rowA] = iA;
        if (b2A - bA < MARGIN_COARSE) { int p = atomicAdd(&d_flagCnt, 1); d_flagList[p] = rowA; }
        int rowB = rowA + 8;
        d_idx[rowB] = iB;
        if (b2B - bB < MARGIN_COARSE) { int p = atomicAdd(&d_flagCnt, 1); d_flagList[p] = rowB; }
    }
}

// ---------------- Kernel 2: exact fp32 rescore (warp per flagged row) ----------------
__global__ __launch_bounds__(256, 1)
void rescore_kernel(const float* __restrict__ x) {
    int warp = threadIdx.x >> 5, lane = threadIdx.x & 31;
    int cnt = d_flagCnt;
    for (int i = blockIdx.x * 8 + warp; i < cnt; i += gridDim.x * 8) {
        int row = d_flagList[i];
        float xr[D];
        const float4* xp = (const float4*)(x + row * D);
        #pragma unroll
        for (int j = 0; j < 16; j++) {
            float4 v = xp[j];
            xr[4*j] = v.x; xr[4*j+1] = v.y; xr[4*j+2] = v.z; xr[4*j+3] = v.w;
        }
        float b = 3.4e38f, b2 = 3.4e38f; int bi = 0;
        for (int j = 0; j < 32; j++) {
            int k = lane + 32 * j;
            const float4* ep = (const float4*)(d_eT + k * D);
            float s0 = 0.0f, s1 = 0.0f;
            #pragma unroll
            for (int qq = 0; qq < 16; qq += 2) {
                float4 e0 = ep[qq], e1 = ep[qq + 1];
                s0 += xr[4*qq]   * e0.x + xr[4*qq+1] * e0.y + xr[4*qq+2] * e0.z + xr[4*qq+3] * e0.w;
                s1 += xr[4*qq+4] * e1.x + xr[4*qq+5] * e1.y + xr[4*qq+6] * e1.z + xr[4*qq+7] * e1.w;
            }
            float dist = d_en[k] - 2.0f * (s0 + s1);
            if (dist < b) { b2 = b; b = dist; bi = k; } else if (dist < b2) b2 = dist;
        }
        #pragma unroll
        for (int off = 16; off > 0; off >>= 1) {
            float ov = __shfl_xor_sync(0xffffffff, b, off);
            float ov2 = __shfl_xor_sync(0xffffffff, b2, off);
            int   oi = __shfl_xor_sync(0xffffffff, bi, off);
            if (ov < b || (ov == b && oi < bi)) { b2 = fminf(b, ov2); b = ov; bi = oi; }
            else b2 = fminf(b2, ov);
        }
        if (lane == 0) {
            d_idx[row] = bi;
            if (b2 - b < MARGIN_TIE) { int p = atomicAdd(&d_flag2Cnt, 1); d_flag2List[p] = row; }
        }
    }
}

// ---------------- Kernel 3: fp64 reference-rounding refine (tie rows) ----------------
__global__ __launch_bounds__(256, 1)
void refine64_kernel(const float* __restrict__ x) {
    __shared__ float sx[D];
    __shared__ float sxn;
    __shared__ float rv[256];
    __shared__ int   ri[256];
    int tid = threadIdx.x;

    int cnt = d_flag2Cnt;
    for (int i = blockIdx.x; i < cnt; i += gridDim.x) {
        int row = d_flag2List[i];
        if (tid < D / 4) {
            float4 v = *(const float4*)(x + row * D + 4 * tid);
            sx[4*tid] = v.x; sx[4*tid+1] = v.y; sx[4*tid+2] = v.z; sx[4*tid+3] = v.w;
        }
        __syncthreads();
        if (tid == 0) {
            float a = 0.0f;
            for (int dd = 0; dd < D; dd++)
                a = __fadd_rn(a, __fmul_rn(sx[dd], sx[dd]));
            sxn = a;
        }
        __syncthreads();
        float xn = sxn;

        int k0 = tid * 4;
        const float* e0 = d_eT + (k0 + 0) * D;
        const float* e1 = d_eT + (k0 + 1) * D;
        const float* e2 = d_eT + (k0 + 2) * D;
        const float* e3 = d_eT + (k0 + 3) * D;
        double s0 = 0.0, s1 = 0.0, s2 = 0.0, s3 = 0.0;
        #pragma unroll 4
        for (int dd = 0; dd < D; dd++) {
            double xv = (double)sx[dd];
            s0 = fma(xv, (double)e0[dd], s0);
            s1 = fma(xv, (double)e1[dd], s1);
            s2 = fma(xv, (double)e2[dd], s2);
            s3 = fma(xv, (double)e3[dd], s3);
        }
        float bv = 3.4e38f; int bi = 0;
        double ss[4] = {s0, s1, s2, s3};
        #pragma unroll
        for (int t = 0; t < 4; t++) {
            float s2f = (float)(2.0 * ss[t]);
            float t1 = __fadd_rn(xn, d_en[k0 + t]);
            float dist = __fsub_rn(t1, s2f);
            if (dist < bv) { bv = dist; bi = k0 + t; }
        }
        rv[tid] = bv; ri[tid] = bi;
        __syncthreads();
        for (int off = 128; off > 0; off >>= 1) {
            if (tid < off) {
                float ov = rv[tid + off]; int oi = ri[tid + off];
                if (ov < rv[tid] || (ov == rv[tid] && oi < ri[tid])) {
                    rv[tid] = ov; ri[tid] = oi;
                }
            }
            __syncthreads();
        }
        if (tid == 0) d_idx[row] = ri[0];
        __syncthreads();
    }
}

// ---------------- Kernel 4: gather + straight-through + loss ----------------
__global__ void out_kernel(const float* __restrict__ x, float* __restrict__ out) {
    int t = blockIdx.x * blockDim.x + threadIdx.x;   // float4 index
    int r = t >> 4, j = t & 15;
    int idx = d_idx[r];
    float4 xv = ((const float4*)x)[t];
    float4 qv = *(const float4*)(d_eT + idx * D + 4 * j);
    float dx = qv.x - xv.x, dy = qv.y - xv.y, dz = qv.z - xv.z, dw = qv.w - xv.w;
    ((float4*)out)[t] = make_float4(xv.x + dx, xv.y + dy, xv.z + dz, xv.w + dw);
    float v = dx * dx + dy * dy + dz * dz + dw * dw;

    #pragma unroll
    for (int off = 16; off > 0; off >>= 1) v += __shfl_xor_sync(0xffffffff, v, off);
    __shared__ float ws[8];
    int wid = threadIdx.x >> 5, lid = threadIdx.x & 31;
    if (lid == 0) ws[wid] = v;
    __syncthreads();
    if (threadIdx.x == 0) {
        float s = 0.0f;
        #pragma unroll
        for (int i = 0; i < 8; i++) s += ws[i];
        atomicAdd(&d_lossAcc, s);
    }
}

// ---------------- Kernel 5: finalize loss ----------------
__global__ void fin_kernel(float* __restrict__ out, int out_size) {
    out[out_size - 1] = 1.25f * d_lossAcc * (1.0f / (float)(N_ROWS * D));
}

extern "C" void kernel_launch(void* const* d_in, const int* in_sizes, int n_in,
                              void* d_out, int out_size) {
    const float* x   = (const float*)d_in[0];
    const float* emb = (const float*)d_in[1];
    float* out = (float*)d_out;

    prep_kernel<<<4, 256>>>(emb);
    gemm_argmin_kernel<<<N_ROWS / TM, 256, S_TOTAL>>>(x);
    rescore_kernel<<<96, 256>>>(x);
    refine64_kernel<<<64, 256>>>(x);
    out_kernel<<<(N_ROWS * D / 4) / 256, 256>>>(x, out);
    fin_kernel<<<1, 1>>>(out, out_size);
}